// round 1
// baseline (speedup 1.0000x reference)
#include <cuda_runtime.h>
#include <math.h>

// Problem constants
#define Bq   8
#define Lq   1024
#define Eq   512
#define Hq   8
#define HDq  64
#define FFq  2048
#define Mq   (Bq*Lq)          // 8192 tokens

// ---------------- scratch (static device globals; allocation-free) ----------
__device__ float g_x [Mq*Eq];        // 16 MB  current activations
__device__ float g_qk[Mq*1024];      // 32 MB  q|k projections (2E per token)
__device__ float g_sv[Bq*Hq*Lq];     //        per-(b,h,i) 0.125/sum(exp)
__device__ float g_A [Bq*Lq*Lq];     // 32 MB  head-avg attn, then W in place
__device__ float g_t [Mq*Eq];        // 16 MB  sa / ff temp
__device__ float g_h [Mq*FFq];       // 64 MB  FFN hidden

// ---------------- helpers ----------------------------------------------------
__device__ __forceinline__ float warp_sum(float s){
    #pragma unroll
    for (int o=16;o;o>>=1) s += __shfl_xor_sync(0xffffffffu, s, o);
    return s;
}

// ============================================================================
// GEMM NT:  C[M,N] = A[M,K] * B[N,K]^T (+bias, optional relu)
// 128x128 tile, BK=8, 256 threads, 8x8 per thread
// ============================================================================
template<int RELU>
__global__ __launch_bounds__(256) void gemm_nt(
    const float* __restrict__ A, const float* __restrict__ Bm,
    const float* __restrict__ bias, float* __restrict__ C,
    int M, int N, int K)
{
    __shared__ __align__(16) float As[8][128];
    __shared__ __align__(16) float Bs[8][128];
    const int bm = blockIdx.y * 128, bn = blockIdx.x * 128;
    const int t  = threadIdx.x;
    const int ty = t >> 4, tx = t & 15;
    const int lr = t >> 1, lc = (t & 1) * 4;

    float acc[8][8];
    #pragma unroll
    for (int i=0;i<8;i++)
        #pragma unroll
        for (int j=0;j<8;j++) acc[i][j] = 0.f;

    const float* Ap = A  + (size_t)(bm + lr) * K + lc;
    const float* Bp = Bm + (size_t)(bn + lr) * K + lc;

    for (int k0 = 0; k0 < K; k0 += 8){
        float4 a4 = *(const float4*)(Ap + k0);
        float4 b4 = *(const float4*)(Bp + k0);
        As[lc+0][lr]=a4.x; As[lc+1][lr]=a4.y; As[lc+2][lr]=a4.z; As[lc+3][lr]=a4.w;
        Bs[lc+0][lr]=b4.x; Bs[lc+1][lr]=b4.y; Bs[lc+2][lr]=b4.z; Bs[lc+3][lr]=b4.w;
        __syncthreads();
        #pragma unroll
        for (int kk=0; kk<8; kk++){
            const float4* A4 = (const float4*)As[kk];
            const float4* B4 = (const float4*)Bs[kk];
            float4 a0 = A4[ty],  a1 = A4[16+ty];
            float4 b0 = B4[tx],  b1 = B4[16+tx];
            float ar[8] = {a0.x,a0.y,a0.z,a0.w, a1.x,a1.y,a1.z,a1.w};
            float br[8] = {b0.x,b0.y,b0.z,b0.w, b1.x,b1.y,b1.z,b1.w};
            #pragma unroll
            for (int i=0;i<8;i++)
                #pragma unroll
                for (int j=0;j<8;j++) acc[i][j] = fmaf(ar[i], br[j], acc[i][j]);
        }
        __syncthreads();
    }

    #pragma unroll
    for (int i=0;i<8;i++){
        int r = bm + ((i<4) ? ty*4 + i : 64 + ty*4 + (i-4));
        #pragma unroll
        for (int jj=0;jj<2;jj++){
            int c = bn + jj*64 + tx*4;
            float4 v = make_float4(acc[i][jj*4+0],acc[i][jj*4+1],acc[i][jj*4+2],acc[i][jj*4+3]);
            if (bias){ v.x += bias[c]; v.y += bias[c+1]; v.z += bias[c+2]; v.w += bias[c+3]; }
            if (RELU){ v.x=fmaxf(v.x,0.f); v.y=fmaxf(v.y,0.f); v.z=fmaxf(v.z,0.f); v.w=fmaxf(v.w,0.f); }
            *(float4*)(C + (size_t)r*N + c) = v;
        }
    }
}

// ============================================================================
// GEMM NN (batched via z):  C = A[M,K] * B[K,N], optional causal K cutoff
// ============================================================================
__global__ __launch_bounds__(256) void gemm_nn(
    const float* __restrict__ A, const float* __restrict__ Bm, float* __restrict__ C,
    int M, int N, int K, long sA, long sB, long sC, int causal)
{
    __shared__ __align__(16) float As[8][128];
    __shared__ __align__(16) float Bs[8][128];
    const float* Ab = A  + (size_t)blockIdx.z * sA;
    const float* Bb = Bm + (size_t)blockIdx.z * sB;
    float*       Cb = C  + (size_t)blockIdx.z * sC;
    const int bm = blockIdx.y * 128, bn = blockIdx.x * 128;
    const int t  = threadIdx.x;
    const int ty = t >> 4, tx = t & 15;
    const int lrA = t >> 1,  lcA = (t & 1) * 4;
    const int lkB = t >> 5,  lcB = (t & 31) * 4;

    float acc[8][8];
    #pragma unroll
    for (int i=0;i<8;i++)
        #pragma unroll
        for (int j=0;j<8;j++) acc[i][j] = 0.f;

    int kend = causal ? min(K, bm + 128) : K;
    for (int k0 = 0; k0 < kend; k0 += 8){
        float4 a4 = *(const float4*)(Ab + (size_t)(bm+lrA)*K + k0 + lcA);
        As[lcA+0][lrA]=a4.x; As[lcA+1][lrA]=a4.y; As[lcA+2][lrA]=a4.z; As[lcA+3][lrA]=a4.w;
        *(float4*)&Bs[lkB][lcB] = *(const float4*)(Bb + (size_t)(k0+lkB)*N + bn + lcB);
        __syncthreads();
        #pragma unroll
        for (int kk=0; kk<8; kk++){
            const float4* A4 = (const float4*)As[kk];
            const float4* B4 = (const float4*)Bs[kk];
            float4 a0 = A4[ty],  a1 = A4[16+ty];
            float4 b0 = B4[tx],  b1 = B4[16+tx];
            float ar[8] = {a0.x,a0.y,a0.z,a0.w, a1.x,a1.y,a1.z,a1.w};
            float br[8] = {b0.x,b0.y,b0.z,b0.w, b1.x,b1.y,b1.z,b1.w};
            #pragma unroll
            for (int i=0;i<8;i++)
                #pragma unroll
                for (int j=0;j<8;j++) acc[i][j] = fmaf(ar[i], br[j], acc[i][j]);
        }
        __syncthreads();
    }

    #pragma unroll
    for (int i=0;i<8;i++){
        int r = bm + ((i<4) ? ty*4 + i : 64 + ty*4 + (i-4));
        #pragma unroll
        for (int jj=0;jj<2;jj++){
            int c = bn + jj*64 + tx*4;
            float4 v = make_float4(acc[i][jj*4+0],acc[i][jj*4+1],acc[i][jj*4+2],acc[i][jj*4+3]);
            *(float4*)(Cb + (size_t)r*N + c) = v;
        }
    }
}

// ============================================================================
// Attention pass 1: per (b,h,i) compute 0.125 / sum_j exp(q.k/8)
// Block: 128 query rows of one (b,h); tiles of 64 j.
// ============================================================================
__global__ __launch_bounds__(256) void attn_pass1(
    const float* __restrict__ qk, float* __restrict__ sinv)
{
    __shared__ __align__(16) float Qs[64][128];   // [kk][row]
    __shared__ __align__(16) float Ks[64][64];    // [kk][col]  (reused for reduction)
    const int bh = blockIdx.x;
    const int i0 = blockIdx.y * 128;
    const int b  = bh >> 3,  h = bh & 7;
    const int t  = threadIdx.x, ty = t >> 4, tx = t & 15;
    const float* qbase = qk + ((size_t)b*Lq)*1024 + h*64;
    const float* kbase = qbase + 512;

    #pragma unroll
    for (int u=0;u<8;u++){
        int idx = t + 256*u;
        int r = idx >> 4, c = (idx & 15) * 4;
        float4 q4 = *(const float4*)(qbase + (size_t)(i0+r)*1024 + c);
        Qs[c+0][r]=q4.x; Qs[c+1][r]=q4.y; Qs[c+2][r]=q4.z; Qs[c+3][r]=q4.w;
    }

    float esum[8] = {0,0,0,0,0,0,0,0};
    for (int j0 = 0; j0 < Lq; j0 += 64){
        __syncthreads();
        #pragma unroll
        for (int u=0;u<4;u++){
            int idx = t + 256*u;
            int r = idx >> 4, c = (idx & 15) * 4;
            float4 k4 = *(const float4*)(kbase + (size_t)(j0+r)*1024 + c);
            Ks[c+0][r]=k4.x; Ks[c+1][r]=k4.y; Ks[c+2][r]=k4.z; Ks[c+3][r]=k4.w;
        }
        __syncthreads();
        float acc[8][4];
        #pragma unroll
        for (int i=0;i<8;i++)
            #pragma unroll
            for (int j=0;j<4;j++) acc[i][j] = 0.f;
        #pragma unroll 8
        for (int kk=0; kk<64; kk++){
            const float4* Q4 = (const float4*)Qs[kk];
            const float4* K4 = (const float4*)Ks[kk];
            float4 a0 = Q4[ty], a1 = Q4[16+ty];
            float4 b0 = K4[tx];
            float ar[8] = {a0.x,a0.y,a0.z,a0.w, a1.x,a1.y,a1.z,a1.w};
            float br[4] = {b0.x,b0.y,b0.z,b0.w};
            #pragma unroll
            for (int i=0;i<8;i++)
                #pragma unroll
                for (int j=0;j<4;j++) acc[i][j] = fmaf(ar[i], br[j], acc[i][j]);
        }
        #pragma unroll
        for (int i=0;i<8;i++)
            #pragma unroll
            for (int j=0;j<4;j++) esum[i] += __expf(acc[i][j] * 0.125f);
    }

    __syncthreads();
    float* red = &Ks[0][0];                    // 128*16 floats fit in Ks
    #pragma unroll
    for (int i=0;i<8;i++){
        int r = (i<4) ? ty*4 + i : 64 + ty*4 + (i-4);
        red[r*16 + tx] = esum[i];
    }
    __syncthreads();
    if (t < 128){
        float s = 0.f;
        #pragma unroll
        for (int q=0;q<16;q++) s += red[t*16 + q];
        sinv[(size_t)bh*Lq + i0 + t] = 0.125f / s;   // folds /H head-average
    }
}

// ============================================================================
// Attention pass 2: A[b,i,j] = (1/H) sum_h exp(q.k/8) * sinv  (causal tiles only)
// ============================================================================
__global__ __launch_bounds__(256) void attn_pass2(
    const float* __restrict__ qk, const float* __restrict__ sinv, float* __restrict__ A)
{
    const int j0 = blockIdx.x * 64;
    const int i0 = blockIdx.y * 128;
    const int b  = blockIdx.z;
    if (j0 >= i0 + 128) return;                  // fully above diagonal -> W=0 there
    __shared__ __align__(16) float Qs[64][128];
    __shared__ __align__(16) float Ks[64][64];
    const int t = threadIdx.x, ty = t >> 4, tx = t & 15;
    const float* qb0 = qk + ((size_t)b*Lq)*1024;

    float accA[8][4];
    #pragma unroll
    for (int i=0;i<8;i++)
        #pragma unroll
        for (int j=0;j<4;j++) accA[i][j] = 0.f;

    for (int h=0; h<Hq; h++){
        __syncthreads();
        const float* qbase = qb0 + h*64;
        const float* kbase = qb0 + 512 + h*64;
        #pragma unroll
        for (int u=0;u<8;u++){
            int idx = t + 256*u;
            int r = idx >> 4, c = (idx & 15) * 4;
            float4 q4 = *(const float4*)(qbase + (size_t)(i0+r)*1024 + c);
            Qs[c+0][r]=q4.x; Qs[c+1][r]=q4.y; Qs[c+2][r]=q4.z; Qs[c+3][r]=q4.w;
        }
        #pragma unroll
        for (int u=0;u<4;u++){
            int idx = t + 256*u;
            int r = idx >> 4, c = (idx & 15) * 4;
            float4 k4 = *(const float4*)(kbase + (size_t)(j0+r)*1024 + c);
            Ks[c+0][r]=k4.x; Ks[c+1][r]=k4.y; Ks[c+2][r]=k4.z; Ks[c+3][r]=k4.w;
        }
        __syncthreads();
        float acc[8][4];
        #pragma unroll
        for (int i=0;i<8;i++)
            #pragma unroll
            for (int j=0;j<4;j++) acc[i][j] = 0.f;
        #pragma unroll 8
        for (int kk=0; kk<64; kk++){
            const float4* Q4 = (const float4*)Qs[kk];
            const float4* K4 = (const float4*)Ks[kk];
            float4 a0 = Q4[ty], a1 = Q4[16+ty];
            float4 b0 = K4[tx];
            float ar[8] = {a0.x,a0.y,a0.z,a0.w, a1.x,a1.y,a1.z,a1.w};
            float br[4] = {b0.x,b0.y,b0.z,b0.w};
            #pragma unroll
            for (int i=0;i<8;i++)
                #pragma unroll
                for (int j=0;j<4;j++) acc[i][j] = fmaf(ar[i], br[j], acc[i][j]);
        }
        const float* sp = sinv + ((size_t)(b*Hq + h))*Lq + i0;
        #pragma unroll
        for (int i=0;i<8;i++){
            int r = (i<4) ? ty*4 + i : 64 + ty*4 + (i-4);
            float si = sp[r];
            #pragma unroll
            for (int j=0;j<4;j++) accA[i][j] += __expf(acc[i][j] * 0.125f) * si;
        }
    }

    #pragma unroll
    for (int i=0;i<8;i++){
        int r = (i<4) ? ty*4 + i : 64 + ty*4 + (i-4);
        float4 v = make_float4(accA[i][0],accA[i][1],accA[i][2],accA[i][3]);
        *(float4*)(A + ((size_t)(b*Lq) + i0 + r)*Lq + j0 + tx*4) = v;
    }
}

// ============================================================================
// W = softmax_j<=i ( A + exp(-(i-j)*0.1) ), strict-causal zeros elsewhere.
// In place on A. One block per (b,i) row.
// ============================================================================
__global__ __launch_bounds__(256) void make_w(float* __restrict__ A)
{
    const int row = blockIdx.x;
    const int i   = row & (Lq-1);
    float* a = A + (size_t)row * Lq;
    const int t = threadIdx.x;
    float v[4]; float s = 0.f;
    #pragma unroll
    for (int u=0;u<4;u++){
        int j = t + 256*u;
        float val = 0.f;
        if (j <= i){
            float pos = __expf((float)(j - i) * 0.1f);
            val = __expf(a[j] + pos);
        }
        v[u] = val; s += val;
    }
    s = warp_sum(s);
    __shared__ float red[8];
    if ((t & 31) == 0) red[t >> 5] = s;
    __syncthreads();
    float tot = 0.f;
    #pragma unroll
    for (int w=0;w<8;w++) tot += red[w];
    float inv = 1.f / tot;
    #pragma unroll
    for (int u=0;u<4;u++){
        int j = t + 256*u;
        a[j] = v[u] * inv;
    }
}

// ============================================================================
// LayerNorm kernels: one warp per 512-wide row
// ============================================================================
__global__ __launch_bounds__(256) void add_ln2(
    const float* __restrict__ x, const float* __restrict__ y,
    const float* __restrict__ g1, const float* __restrict__ b1,
    const float* __restrict__ g2, const float* __restrict__ b2,
    float* __restrict__ out)
{
    const int row  = blockIdx.x * 8 + (threadIdx.x >> 5);
    const int lane = threadIdx.x & 31;
    const float* xr = x + (size_t)row * Eq;
    const float* yr = y + (size_t)row * Eq;
    float v[16]; float s = 0.f;
    #pragma unroll
    for (int u=0;u<16;u++){ int c = lane + u*32; v[u] = xr[c] + yr[c]; s += v[u]; }
    s = warp_sum(s);
    float mean = s * (1.0f/Eq);
    float sq = 0.f;
    #pragma unroll
    for (int u=0;u<16;u++){ float d = v[u]-mean; sq += d*d; }
    sq = warp_sum(sq);
    float rstd = rsqrtf(sq*(1.0f/Eq) + 1e-5f);
    float s2 = 0.f;
    #pragma unroll
    for (int u=0;u<16;u++){ int c = lane + u*32; v[u] = (v[u]-mean)*rstd*g1[c] + b1[c]; s2 += v[u]; }
    s2 = warp_sum(s2);
    float m2 = s2 * (1.0f/Eq);
    float q2 = 0.f;
    #pragma unroll
    for (int u=0;u<16;u++){ float d = v[u]-m2; q2 += d*d; }
    q2 = warp_sum(q2);
    float r2 = rsqrtf(q2*(1.0f/Eq) + 1e-5f);
    float* orow = out + (size_t)row * Eq;
    #pragma unroll
    for (int u=0;u<16;u++){ int c = lane + u*32; orow[c] = (v[u]-m2)*r2*g2[c] + b2[c]; }
}

__global__ __launch_bounds__(256) void add_ln1(
    const float* __restrict__ x, const float* __restrict__ y,
    const float* __restrict__ g, const float* __restrict__ b,
    float* __restrict__ out)
{
    const int row  = blockIdx.x * 8 + (threadIdx.x >> 5);
    const int lane = threadIdx.x & 31;
    const float* xr = x + (size_t)row * Eq;
    const float* yr = y + (size_t)row * Eq;
    float v[16]; float s = 0.f;
    #pragma unroll
    for (int u=0;u<16;u++){ int c = lane + u*32; v[u] = xr[c] + yr[c]; s += v[u]; }
    s = warp_sum(s);
    float mean = s * (1.0f/Eq);
    float sq = 0.f;
    #pragma unroll
    for (int u=0;u<16;u++){ float d = v[u]-mean; sq += d*d; }
    sq = warp_sum(sq);
    float rstd = rsqrtf(sq*(1.0f/Eq) + 1e-5f);
    float* orow = out + (size_t)row * Eq;
    #pragma unroll
    for (int u=0;u<16;u++){ int c = lane + u*32; orow[c] = (v[u]-mean)*rstd*g[c] + b[c]; }
}

// ============================================================================
// Launch
// ============================================================================
extern "C" void kernel_launch(void* const* d_in, const int* in_sizes, int n_in,
                              void* d_out, int out_size)
{
    const float* input = (const float*)d_in[0];
    const float* Wqkv  = (const float*)d_in[1];
    const float* bqkv  = (const float*)d_in[2];
    const float* W1    = (const float*)d_in[3];
    const float* b1    = (const float*)d_in[4];
    const float* W2    = (const float*)d_in[5];
    const float* b2    = (const float*)d_in[6];
    const float* g1    = (const float*)d_in[7];
    const float* bt1   = (const float*)d_in[8];
    const float* g2    = (const float*)d_in[9];
    const float* bt2   = (const float*)d_in[10];
    const float* g3    = (const float*)d_in[11];
    const float* bt3   = (const float*)d_in[12];

    float *x, *qk, *sv, *A, *tb, *hb;
    cudaGetSymbolAddress((void**)&x,  g_x);
    cudaGetSymbolAddress((void**)&qk, g_qk);
    cudaGetSymbolAddress((void**)&sv, g_sv);
    cudaGetSymbolAddress((void**)&A,  g_A);
    cudaGetSymbolAddress((void**)&tb, g_t);
    cudaGetSymbolAddress((void**)&hb, g_h);

    cudaMemcpyAsync(x, input, (size_t)Mq*Eq*sizeof(float),
                    cudaMemcpyDeviceToDevice, 0);

    for (int d = 0; d < 4; d++){
        const float* Wq = Wqkv + (size_t)d * 1536 * 512;
        const float* bq = bqkv + (size_t)d * 1536;

        // q|k projection: only first 2E rows of Wqkv needed (v is dead in ref)
        gemm_nt<0><<<dim3(1024/128, Mq/128), 256>>>(x, Wq, bq, qk, Mq, 1024, 512);

        // per-head softmax denominators, then head-averaged A (causal tiles)
        attn_pass1<<<dim3(Bq*Hq, Lq/128), 256>>>(qk, sv);
        attn_pass2<<<dim3(Lq/64, Lq/128, Bq), 256>>>(qk, sv, A);

        // second softmax with causal mask + relative-position bias (in place)
        make_w<<<Bq*Lq, 256>>>(A);

        // sa = W @ x (values are RAW x), causal k-tile skip
        gemm_nn<<<dim3(Eq/128, Lq/128, Bq), 256>>>(A, x, tb, Lq, Eq, Lq,
                                                   (long)Lq*Lq, (long)Lq*Eq, (long)Lq*Eq, 1);

        // x = LN2(LN1(x + sa))   (cross-attn block is a double-LN no-op)
        add_ln2<<<Mq/8, 256>>>(x, tb,
                               g1 + d*Eq, bt1 + d*Eq,
                               g2 + d*Eq, bt2 + d*Eq, x);

        // FFN
        gemm_nt<1><<<dim3(FFq/128, Mq/128), 256>>>(x, W1 + (size_t)d*FFq*Eq,
                                                   b1 + (size_t)d*FFq, hb, Mq, FFq, Eq);
        gemm_nt<0><<<dim3(Eq/128, Mq/128), 256>>>(hb, W2 + (size_t)d*Eq*FFq,
                                                  b2 + (size_t)d*Eq, tb, Mq, Eq, FFq);

        float* outp = (d == 3) ? (float*)d_out : x;
        add_ln1<<<Mq/8, 256>>>(x, tb, g3 + d*Eq, bt3 + d*Eq, outp);
    }
}

// round 2
// speedup vs baseline: 1.5969x; 1.5969x over previous
#include <cuda_runtime.h>
#include <cuda_bf16.h>
#include <math.h>
#include <stdint.h>

// Problem constants
#define Bq   8
#define Lq   1024
#define Eq   512
#define Hq   8
#define FFq  2048
#define Mq   (Bq*Lq)          // 8192 tokens

// ---------------- scratch (static device globals; allocation-free) ----------
__device__ float g_x [Mq*Eq];        // current activations
__device__ float g_qk[Mq*1024];      // q|k projections (2E per token)
__device__ float g_sv[Bq*Hq*Lq];     // per-(b,h,i) 0.125/sum(exp)
__device__ float g_A [Bq*Lq*Lq];     // head-avg attn, then W in place
__device__ float g_t [Mq*Eq];        // sa / ff temp
__device__ float g_h [Mq*FFq];       // FFN hidden
__device__ float g_xt[Bq*Eq*Lq];     // per-batch x^T for W@x GEMM

// ---------------- helpers ----------------------------------------------------
__device__ __forceinline__ float warp_sum(float s){
    #pragma unroll
    for (int o=16;o;o>>=1) s += __shfl_xor_sync(0xffffffffu, s, o);
    return s;
}

// split fp32 pair into packed bf16 (hi) + packed bf16 residual (lo)
__device__ __forceinline__ void bsplit(float x0, float x1, uint32_t& hi, uint32_t& lo){
    __nv_bfloat16 h0 = __float2bfloat16_rn(x0);
    __nv_bfloat16 h1 = __float2bfloat16_rn(x1);
    __nv_bfloat16 l0 = __float2bfloat16_rn(x0 - __bfloat162float(h0));
    __nv_bfloat16 l1 = __float2bfloat16_rn(x1 - __bfloat162float(h1));
    hi = (uint32_t)__bfloat16_as_ushort(h0) | ((uint32_t)__bfloat16_as_ushort(h1) << 16);
    lo = (uint32_t)__bfloat16_as_ushort(l0) | ((uint32_t)__bfloat16_as_ushort(l1) << 16);
}

__device__ __forceinline__ void mma16816(float* c, const uint32_t* a, const uint32_t* b){
    asm volatile(
        "mma.sync.aligned.m16n8k16.row.col.f32.bf16.bf16.f32 "
        "{%0,%1,%2,%3}, {%4,%5,%6,%7}, {%8,%9}, {%0,%1,%2,%3};\n"
        : "+f"(c[0]), "+f"(c[1]), "+f"(c[2]), "+f"(c[3])
        : "r"(a[0]), "r"(a[1]), "r"(a[2]), "r"(a[3]), "r"(b[0]), "r"(b[1]));
}

// ============================================================================
// Tensor-core GEMM NT (bf16-split x3, fp32 accumulate):
//   C[M,N] = A[M,K] * B[N,K]^T (+bias, optional relu), batched via blockIdx.z
// Block tile 128x128, BK=32, 256 threads (8 warps, 2x4 warp grid, 64x32/warp)
// Smem rows padded to 80B -> conflict-free fragment LDS (verified bank math).
// ============================================================================
template<int RELU>
__global__ __launch_bounds__(256, 2) void mma_gemm(
    const float* __restrict__ A, const float* __restrict__ B,
    const float* __restrict__ bias, float* __restrict__ C,
    int M, int N, int K, long sA, long sB, long sC, int causal)
{
    __shared__ uint32_t sAh[128*20], sAl[128*20], sBh[128*20], sBl[128*20];
    const int bm = blockIdx.y * 128, bn = blockIdx.x * 128;
    const float* Ab = A + (size_t)blockIdx.z * sA;
    const float* Bb = B + (size_t)blockIdx.z * sB;
    float*       Cb = C + (size_t)blockIdx.z * sC;

    const int t    = threadIdx.x;
    const int lane = t & 31, wid = t >> 5;
    const int wm   = wid >> 2, wn = wid & 3;     // 2 x 4 warp grid
    const int gid  = lane >> 2, tig = lane & 3;

    float acc[4][4][4];
    #pragma unroll
    for (int i=0;i<4;i++)
        #pragma unroll
        for (int j=0;j<4;j++)
            #pragma unroll
            for (int q=0;q<4;q++) acc[i][j][q] = 0.f;

    // fill mapping: thread -> (row fr, 16-float segment)
    const int fr = t >> 1;
    const int fc = (t & 1) * 16;
    const float* Afill = Ab + (size_t)(bm + fr) * K + fc;
    const float* Bfill = Bb + (size_t)(bn + fr) * K + fc;
    uint32_t* sAhp = sAh + fr*20 + (t & 1)*8;
    uint32_t* sAlp = sAl + fr*20 + (t & 1)*8;
    uint32_t* sBhp = sBh + fr*20 + (t & 1)*8;
    uint32_t* sBlp = sBl + fr*20 + (t & 1)*8;

    const int kend = causal ? (bm + 128) : K;
    for (int k0 = 0; k0 < kend; k0 += 32){
        float4 a4[4], b4[4];
        #pragma unroll
        for (int j=0;j<4;j++){
            a4[j] = *(const float4*)(Afill + k0 + 4*j);
            b4[j] = *(const float4*)(Bfill + k0 + 4*j);
        }
        __syncthreads();   // previous compute done before overwrite
        #pragma unroll
        for (int j=0;j<4;j++){
            uint32_t h0,l0,h1,l1;
            bsplit(a4[j].x, a4[j].y, h0, l0);
            bsplit(a4[j].z, a4[j].w, h1, l1);
            sAhp[2*j] = h0; sAhp[2*j+1] = h1;
            sAlp[2*j] = l0; sAlp[2*j+1] = l1;
            bsplit(b4[j].x, b4[j].y, h0, l0);
            bsplit(b4[j].z, b4[j].w, h1, l1);
            sBhp[2*j] = h0; sBhp[2*j+1] = h1;
            sBlp[2*j] = l0; sBlp[2*j+1] = l1;
        }
        __syncthreads();

        #pragma unroll
        for (int ks=0; ks<2; ks++){
            const int ci = tig + ks*8;
            uint32_t bhf[4][2], blf[4][2];
            #pragma unroll
            for (int ni=0;ni<4;ni++){
                int n = (wn*32 + ni*8 + gid)*20;
                bhf[ni][0] = sBh[n + ci];  bhf[ni][1] = sBh[n + ci + 4];
                blf[ni][0] = sBl[n + ci];  blf[ni][1] = sBl[n + ci + 4];
            }
            #pragma unroll
            for (int mi=0;mi<4;mi++){
                int m0 = (wm*64 + mi*16 + gid)*20;
                uint32_t ah[4] = {sAh[m0+ci], sAh[m0+160+ci], sAh[m0+ci+4], sAh[m0+160+ci+4]};
                uint32_t al[4] = {sAl[m0+ci], sAl[m0+160+ci], sAl[m0+ci+4], sAl[m0+160+ci+4]};
                #pragma unroll
                for (int ni=0;ni<4;ni++){
                    mma16816(acc[mi][ni], ah, bhf[ni]);
                    mma16816(acc[mi][ni], ah, blf[ni]);
                    mma16816(acc[mi][ni], al, bhf[ni]);
                }
            }
        }
    }

    // epilogue
    #pragma unroll
    for (int mi=0;mi<4;mi++){
        int row = bm + wm*64 + mi*16 + gid;
        #pragma unroll
        for (int ni=0;ni<4;ni++){
            int col = bn + wn*32 + ni*8 + tig*2;
            float2 v0 = make_float2(acc[mi][ni][0], acc[mi][ni][1]);
            float2 v1 = make_float2(acc[mi][ni][2], acc[mi][ni][3]);
            if (bias){
                float2 bb = *(const float2*)(bias + col);
                v0.x += bb.x; v0.y += bb.y; v1.x += bb.x; v1.y += bb.y;
            }
            if (RELU){
                v0.x=fmaxf(v0.x,0.f); v0.y=fmaxf(v0.y,0.f);
                v1.x=fmaxf(v1.x,0.f); v1.y=fmaxf(v1.y,0.f);
            }
            *(float2*)(Cb + (size_t)row    *N + col) = v0;
            *(float2*)(Cb + (size_t)(row+8)*N + col) = v1;
        }
    }
}

// ============================================================================
// Batched transpose: xt[b][e][l] = x[b][l][e]
// ============================================================================
__global__ __launch_bounds__(256) void transpose_x(
    const float* __restrict__ x, float* __restrict__ xt)
{
    __shared__ float tile[32][33];
    const int b  = blockIdx.z;
    const int l0 = blockIdx.y * 32, e0 = blockIdx.x * 32;
    const float* xp  = x  + (size_t)b * Lq * Eq;
    float*       xtp = xt + (size_t)b * Eq * Lq;
    const int tx = threadIdx.x, ty = threadIdx.y;   // 32 x 8
    #pragma unroll
    for (int j=0;j<32;j+=8)
        tile[ty+j][tx] = xp[(size_t)(l0+ty+j)*Eq + e0 + tx];
    __syncthreads();
    #pragma unroll
    for (int j=0;j<32;j+=8)
        xtp[(size_t)(e0+ty+j)*Lq + l0 + tx] = tile[tx][ty+j];
}

// ============================================================================
// Attention pass 1: per (b,h,i) compute 0.125 / sum_j exp(q.k/8)
// ============================================================================
__global__ __launch_bounds__(256) void attn_pass1(
    const float* __restrict__ qk, float* __restrict__ sinv)
{
    __shared__ __align__(16) float Qs[64][128];
    __shared__ __align__(16) float Ks[64][64];
    const int bh = blockIdx.x;
    const int i0 = blockIdx.y * 128;
    const int b  = bh >> 3,  h = bh & 7;
    const int t  = threadIdx.x, ty = t >> 4, tx = t & 15;
    const float* qbase = qk + ((size_t)b*Lq)*1024 + h*64;
    const float* kbase = qbase + 512;

    #pragma unroll
    for (int u=0;u<8;u++){
        int idx = t + 256*u;
        int r = idx >> 4, c = (idx & 15) * 4;
        float4 q4 = *(const float4*)(qbase + (size_t)(i0+r)*1024 + c);
        Qs[c+0][r]=q4.x; Qs[c+1][r]=q4.y; Qs[c+2][r]=q4.z; Qs[c+3][r]=q4.w;
    }

    float esum[8] = {0,0,0,0,0,0,0,0};
    for (int j0 = 0; j0 < Lq; j0 += 64){
        __syncthreads();
        #pragma unroll
        for (int u=0;u<4;u++){
            int idx = t + 256*u;
            int r = idx >> 4, c = (idx & 15) * 4;
            float4 k4 = *(const float4*)(kbase + (size_t)(j0+r)*1024 + c);
            Ks[c+0][r]=k4.x; Ks[c+1][r]=k4.y; Ks[c+2][r]=k4.z; Ks[c+3][r]=k4.w;
        }
        __syncthreads();
        float acc[8][4];
        #pragma unroll
        for (int i=0;i<8;i++)
            #pragma unroll
            for (int j=0;j<4;j++) acc[i][j] = 0.f;
        #pragma unroll 8
        for (int kk=0; kk<64; kk++){
            const float4* Q4 = (const float4*)Qs[kk];
            const float4* K4 = (const float4*)Ks[kk];
            float4 a0 = Q4[ty], a1 = Q4[16+ty];
            float4 b0 = K4[tx];
            float ar[8] = {a0.x,a0.y,a0.z,a0.w, a1.x,a1.y,a1.z,a1.w};
            float br[4] = {b0.x,b0.y,b0.z,b0.w};
            #pragma unroll
            for (int i=0;i<8;i++)
                #pragma unroll
                for (int j=0;j<4;j++) acc[i][j] = fmaf(ar[i], br[j], acc[i][j]);
        }
        #pragma unroll
        for (int i=0;i<8;i++)
            #pragma unroll
            for (int j=0;j<4;j++) esum[i] += __expf(acc[i][j] * 0.125f);
    }

    __syncthreads();
    float* red = &Ks[0][0];
    #pragma unroll
    for (int i=0;i<8;i++){
        int r = (i<4) ? ty*4 + i : 64 + ty*4 + (i-4);
        red[r*16 + tx] = esum[i];
    }
    __syncthreads();
    if (t < 128){
        float s = 0.f;
        #pragma unroll
        for (int q=0;q<16;q++) s += red[t*16 + q];
        sinv[(size_t)bh*Lq + i0 + t] = 0.125f / s;
    }
}

// ============================================================================
// Attention pass 2: A[b,i,j] = sum_h exp(q.k/8) * sinv  (causal tiles only)
// ============================================================================
__global__ __launch_bounds__(256) void attn_pass2(
    const float* __restrict__ qk, const float* __restrict__ sinv, float* __restrict__ A)
{
    const int j0 = blockIdx.x * 64;
    const int i0 = blockIdx.y * 128;
    const int b  = blockIdx.z;
    if (j0 >= i0 + 128) return;
    __shared__ __align__(16) float Qs[64][128];
    __shared__ __align__(16) float Ks[64][64];
    const int t = threadIdx.x, ty = t >> 4, tx = t & 15;
    const float* qb0 = qk + ((size_t)b*Lq)*1024;

    float accA[8][4];
    #pragma unroll
    for (int i=0;i<8;i++)
        #pragma unroll
        for (int j=0;j<4;j++) accA[i][j] = 0.f;

    for (int h=0; h<Hq; h++){
        __syncthreads();
        const float* qbase = qb0 + h*64;
        const float* kbase = qb0 + 512 + h*64;
        #pragma unroll
        for (int u=0;u<8;u++){
            int idx = t + 256*u;
            int r = idx >> 4, c = (idx & 15) * 4;
            float4 q4 = *(const float4*)(qbase + (size_t)(i0+r)*1024 + c);
            Qs[c+0][r]=q4.x; Qs[c+1][r]=q4.y; Qs[c+2][r]=q4.z; Qs[c+3][r]=q4.w;
        }
        #pragma unroll
        for (int u=0;u<4;u++){
            int idx = t + 256*u;
            int r = idx >> 4, c = (idx & 15) * 4;
            float4 k4 = *(const float4*)(kbase + (size_t)(j0+r)*1024 + c);
            Ks[c+0][r]=k4.x; Ks[c+1][r]=k4.y; Ks[c+2][r]=k4.z; Ks[c+3][r]=k4.w;
        }
        __syncthreads();
        float acc[8][4];
        #pragma unroll
        for (int i=0;i<8;i++)
            #pragma unroll
            for (int j=0;j<4;j++) acc[i][j] = 0.f;
        #pragma unroll 8
        for (int kk=0; kk<64; kk++){
            const float4* Q4 = (const float4*)Qs[kk];
            const float4* K4 = (const float4*)Ks[kk];
            float4 a0 = Q4[ty], a1 = Q4[16+ty];
            float4 b0 = K4[tx];
            float ar[8] = {a0.x,a0.y,a0.z,a0.w, a1.x,a1.y,a1.z,a1.w};
            float br[4] = {b0.x,b0.y,b0.z,b0.w};
            #pragma unroll
            for (int i=0;i<8;i++)
                #pragma unroll
                for (int j=0;j<4;j++) acc[i][j] = fmaf(ar[i], br[j], acc[i][j]);
        }
        const float* sp = sinv + ((size_t)(b*Hq + h))*Lq + i0;
        #pragma unroll
        for (int i=0;i<8;i++){
            int r = (i<4) ? ty*4 + i : 64 + ty*4 + (i-4);
            float si = sp[r];
            #pragma unroll
            for (int j=0;j<4;j++) accA[i][j] += __expf(acc[i][j] * 0.125f) * si;
        }
    }

    #pragma unroll
    for (int i=0;i<8;i++){
        int r = (i<4) ? ty*4 + i : 64 + ty*4 + (i-4);
        float4 v = make_float4(accA[i][0],accA[i][1],accA[i][2],accA[i][3]);
        *(float4*)(A + ((size_t)(b*Lq) + i0 + r)*Lq + j0 + tx*4) = v;
    }
}

// ============================================================================
// W = softmax_j<=i ( A + exp(-(i-j)*0.1) ), strict-causal zeros elsewhere.
// ============================================================================
__global__ __launch_bounds__(256) void make_w(float* __restrict__ A)
{
    const int row = blockIdx.x;
    const int i   = row & (Lq-1);
    float* a = A + (size_t)row * Lq;
    const int t = threadIdx.x;
    float v[4]; float s = 0.f;
    #pragma unroll
    for (int u=0;u<4;u++){
        int j = t + 256*u;
        float val = 0.f;
        if (j <= i){
            float pos = __expf((float)(j - i) * 0.1f);
            val = __expf(a[j] + pos);
        }
        v[u] = val; s += val;
    }
    s = warp_sum(s);
    __shared__ float red[8];
    if ((t & 31) == 0) red[t >> 5] = s;
    __syncthreads();
    float tot = 0.f;
    #pragma unroll
    for (int w=0;w<8;w++) tot += red[w];
    float inv = 1.f / tot;
    #pragma unroll
    for (int u=0;u<4;u++){
        int j = t + 256*u;
        a[j] = v[u] * inv;
    }
}

// ============================================================================
// LayerNorm kernels: one warp per 512-wide row
// ============================================================================
__global__ __launch_bounds__(256) void add_ln2(
    const float* __restrict__ x, const float* __restrict__ y,
    const float* __restrict__ g1, const float* __restrict__ b1,
    const float* __restrict__ g2, const float* __restrict__ b2,
    float* __restrict__ out)
{
    const int row  = blockIdx.x * 8 + (threadIdx.x >> 5);
    const int lane = threadIdx.x & 31;
    const float* xr = x + (size_t)row * Eq;
    const float* yr = y + (size_t)row * Eq;
    float v[16]; float s = 0.f;
    #pragma unroll
    for (int u=0;u<16;u++){ int c = lane + u*32; v[u] = xr[c] + yr[c]; s += v[u]; }
    s = warp_sum(s);
    float mean = s * (1.0f/Eq);
    float sq = 0.f;
    #pragma unroll
    for (int u=0;u<16;u++){ float d = v[u]-mean; sq += d*d; }
    sq = warp_sum(sq);
    float rstd = rsqrtf(sq*(1.0f/Eq) + 1e-5f);
    float s2 = 0.f;
    #pragma unroll
    for (int u=0;u<16;u++){ int c = lane + u*32; v[u] = (v[u]-mean)*rstd*g1[c] + b1[c]; s2 += v[u]; }
    s2 = warp_sum(s2);
    float m2 = s2 * (1.0f/Eq);
    float q2 = 0.f;
    #pragma unroll
    for (int u=0;u<16;u++){ float d = v[u]-m2; q2 += d*d; }
    q2 = warp_sum(q2);
    float r2 = rsqrtf(q2*(1.0f/Eq) + 1e-5f);
    float* orow = out + (size_t)row * Eq;
    #pragma unroll
    for (int u=0;u<16;u++){ int c = lane + u*32; orow[c] = (v[u]-m2)*r2*g2[c] + b2[c]; }
}

__global__ __launch_bounds__(256) void add_ln1(
    const float* __restrict__ x, const float* __restrict__ y,
    const float* __restrict__ g, const float* __restrict__ b,
    float* __restrict__ out)
{
    const int row  = blockIdx.x * 8 + (threadIdx.x >> 5);
    const int lane = threadIdx.x & 31;
    const float* xr = x + (size_t)row * Eq;
    const float* yr = y + (size_t)row * Eq;
    float v[16]; float s = 0.f;
    #pragma unroll
    for (int u=0;u<16;u++){ int c = lane + u*32; v[u] = xr[c] + yr[c]; s += v[u]; }
    s = warp_sum(s);
    float mean = s * (1.0f/Eq);
    float sq = 0.f;
    #pragma unroll
    for (int u=0;u<16;u++){ float d = v[u]-mean; sq += d*d; }
    sq = warp_sum(sq);
    float rstd = rsqrtf(sq*(1.0f/Eq) + 1e-5f);
    float* orow = out + (size_t)row * Eq;
    #pragma unroll
    for (int u=0;u<16;u++){ int c = lane + u*32; orow[c] = (v[u]-mean)*rstd*g[c] + b[c]; }
}

// ============================================================================
// Launch
// ============================================================================
extern "C" void kernel_launch(void* const* d_in, const int* in_sizes, int n_in,
                              void* d_out, int out_size)
{
    const float* input = (const float*)d_in[0];
    const float* Wqkv  = (const float*)d_in[1];
    const float* bqkv  = (const float*)d_in[2];
    const float* W1    = (const float*)d_in[3];
    const float* b1    = (const float*)d_in[4];
    const float* W2    = (const float*)d_in[5];
    const float* b2    = (const float*)d_in[6];
    const float* g1    = (const float*)d_in[7];
    const float* bt1   = (const float*)d_in[8];
    const float* g2    = (const float*)d_in[9];
    const float* bt2   = (const float*)d_in[10];
    const float* g3    = (const float*)d_in[11];
    const float* bt3   = (const float*)d_in[12];

    float *x, *qk, *sv, *A, *tb, *hb, *xt;
    cudaGetSymbolAddress((void**)&x,  g_x);
    cudaGetSymbolAddress((void**)&qk, g_qk);
    cudaGetSymbolAddress((void**)&sv, g_sv);
    cudaGetSymbolAddress((void**)&A,  g_A);
    cudaGetSymbolAddress((void**)&tb, g_t);
    cudaGetSymbolAddress((void**)&hb, g_h);
    cudaGetSymbolAddress((void**)&xt, g_xt);

    cudaMemcpyAsync(x, input, (size_t)Mq*Eq*sizeof(float),
                    cudaMemcpyDeviceToDevice, 0);

    for (int d = 0; d < 4; d++){
        const float* Wq = Wqkv + (size_t)d * 1536 * 512;
        const float* bq = bqkv + (size_t)d * 1536;

        // q|k projection: only first 2E rows of Wqkv needed (v is dead in ref)
        mma_gemm<0><<<dim3(1024/128, Mq/128, 1), 256>>>(
            x, Wq, bq, qk, Mq, 1024, 512, 0, 0, 0, 0);

        // per-head softmax denominators, then head-averaged A (causal tiles)
        attn_pass1<<<dim3(Bq*Hq, Lq/128), 256>>>(qk, sv);
        attn_pass2<<<dim3(Lq/64, Lq/128, Bq), 256>>>(qk, sv, A);

        // second softmax with causal mask + relative-position bias (in place)
        make_w<<<Bq*Lq, 256>>>(A);

        // sa = W @ x: transpose x per batch, then NT tensor-core GEMM w/ causal cutoff
        transpose_x<<<dim3(Eq/32, Lq/32, Bq), dim3(32,8)>>>(x, xt);
        mma_gemm<0><<<dim3(Eq/128, Lq/128, Bq), 256>>>(
            A, xt, nullptr, tb, Lq, Eq, Lq,
            (long)Lq*Lq, (long)Eq*Lq, (long)Lq*Eq, 1);

        // x = LN2(LN1(x + sa))   (cross-attn block is a double-LN no-op)
        add_ln2<<<Mq/8, 256>>>(x, tb,
                               g1 + d*Eq, bt1 + d*Eq,
                               g2 + d*Eq, bt2 + d*Eq, x);

        // FFN
        mma_gemm<1><<<dim3(FFq/128, Mq/128, 1), 256>>>(
            x, W1 + (size_t)d*FFq*Eq, b1 + (size_t)d*FFq, hb,
            Mq, FFq, Eq, 0, 0, 0, 0);
        mma_gemm<0><<<dim3(Eq/128, Mq/128, 1), 256>>>(
            hb, W2 + (size_t)d*Eq*FFq, b2 + (size_t)d*Eq, tb,
            Mq, Eq, FFq, 0, 0, 0, 0);

        float* outp = (d == 3) ? (float*)d_out : x;
        add_ln1<<<Mq/8, 256>>>(x, tb, g3 + d*Eq, bt3 + d*Eq, outp);
    }
}

// round 3
// speedup vs baseline: 2.1106x; 1.3217x over previous
#include <cuda_runtime.h>
#include <cuda_bf16.h>
#include <math.h>
#include <stdint.h>

// Problem constants
#define Bq   8
#define Lq   1024
#define Eq   512
#define Hq   8
#define FFq  2048
#define Mq   (Bq*Lq)          // 8192 tokens

// ---------------- scratch (static device globals; allocation-free) ----------
__device__ float g_x [Mq*Eq];        // current activations
__device__ float g_qk[Mq*1024];      // q|k projections (2E per token)
__device__ float g_sv[Bq*Hq*Lq];     // per-(b,h,i) 0.125/sum(exp)
__device__ float g_A [Bq*Lq*Lq];     // head-avg attn, then W in place
__device__ float g_t [Mq*Eq];        // sa / ff temp
__device__ float g_h [Mq*FFq];       // FFN hidden
__device__ float g_xt[Bq*Eq*Lq];     // per-batch x^T for W@x GEMM
__device__ float g_P [(size_t)Bq*Hq*Lq*Lq];  // 268MB per-head exp(logits), causal tiles

// ---------------- helpers ----------------------------------------------------
__device__ __forceinline__ float warp_sum(float s){
    #pragma unroll
    for (int o=16;o;o>>=1) s += __shfl_xor_sync(0xffffffffu, s, o);
    return s;
}

// split fp32 pair into packed bf16 (hi) + packed bf16 residual (lo)
__device__ __forceinline__ void bsplit(float x0, float x1, uint32_t& hi, uint32_t& lo){
    __nv_bfloat16 h0 = __float2bfloat16_rn(x0);
    __nv_bfloat16 h1 = __float2bfloat16_rn(x1);
    __nv_bfloat16 l0 = __float2bfloat16_rn(x0 - __bfloat162float(h0));
    __nv_bfloat16 l1 = __float2bfloat16_rn(x1 - __bfloat162float(h1));
    hi = (uint32_t)__bfloat16_as_ushort(h0) | ((uint32_t)__bfloat16_as_ushort(h1) << 16);
    lo = (uint32_t)__bfloat16_as_ushort(l0) | ((uint32_t)__bfloat16_as_ushort(l1) << 16);
}

__device__ __forceinline__ void mma16816(float* c, const uint32_t* a, const uint32_t* b){
    asm volatile(
        "mma.sync.aligned.m16n8k16.row.col.f32.bf16.bf16.f32 "
        "{%0,%1,%2,%3}, {%4,%5,%6,%7}, {%8,%9}, {%0,%1,%2,%3};\n"
        : "+f"(c[0]), "+f"(c[1]), "+f"(c[2]), "+f"(c[3])
        : "r"(a[0]), "r"(a[1]), "r"(a[2]), "r"(a[3]), "r"(b[0]), "r"(b[1]));
}

// ============================================================================
// Tensor-core GEMM NT (bf16-split x3, fp32 accumulate):
//   C[M,N] = A[M,K] * B[N,K]^T (+bias, optional relu), batched via blockIdx.z
// ============================================================================
template<int RELU>
__global__ __launch_bounds__(256, 2) void mma_gemm(
    const float* __restrict__ A, const float* __restrict__ B,
    const float* __restrict__ bias, float* __restrict__ C,
    int M, int N, int K, long sA, long sB, long sC, int causal)
{
    __shared__ uint32_t sAh[128*20], sAl[128*20], sBh[128*20], sBl[128*20];
    const int bm = blockIdx.y * 128, bn = blockIdx.x * 128;
    const float* Ab = A + (size_t)blockIdx.z * sA;
    const float* Bb = B + (size_t)blockIdx.z * sB;
    float*       Cb = C + (size_t)blockIdx.z * sC;

    const int t    = threadIdx.x;
    const int lane = t & 31, wid = t >> 5;
    const int wm   = wid >> 2, wn = wid & 3;
    const int gid  = lane >> 2, tig = lane & 3;

    float acc[4][4][4];
    #pragma unroll
    for (int i=0;i<4;i++)
        #pragma unroll
        for (int j=0;j<4;j++)
            #pragma unroll
            for (int q=0;q<4;q++) acc[i][j][q] = 0.f;

    const int fr = t >> 1;
    const int fc = (t & 1) * 16;
    const float* Afill = Ab + (size_t)(bm + fr) * K + fc;
    const float* Bfill = Bb + (size_t)(bn + fr) * K + fc;
    uint32_t* sAhp = sAh + fr*20 + (t & 1)*8;
    uint32_t* sAlp = sAl + fr*20 + (t & 1)*8;
    uint32_t* sBhp = sBh + fr*20 + (t & 1)*8;
    uint32_t* sBlp = sBl + fr*20 + (t & 1)*8;

    const int kend = causal ? (bm + 128) : K;
    for (int k0 = 0; k0 < kend; k0 += 32){
        float4 a4[4], b4[4];
        #pragma unroll
        for (int j=0;j<4;j++){
            a4[j] = *(const float4*)(Afill + k0 + 4*j);
            b4[j] = *(const float4*)(Bfill + k0 + 4*j);
        }
        __syncthreads();
        #pragma unroll
        for (int j=0;j<4;j++){
            uint32_t h0,l0,h1,l1;
            bsplit(a4[j].x, a4[j].y, h0, l0);
            bsplit(a4[j].z, a4[j].w, h1, l1);
            sAhp[2*j] = h0; sAhp[2*j+1] = h1;
            sAlp[2*j] = l0; sAlp[2*j+1] = l1;
            bsplit(b4[j].x, b4[j].y, h0, l0);
            bsplit(b4[j].z, b4[j].w, h1, l1);
            sBhp[2*j] = h0; sBhp[2*j+1] = h1;
            sBlp[2*j] = l0; sBlp[2*j+1] = l1;
        }
        __syncthreads();

        #pragma unroll
        for (int ks=0; ks<2; ks++){
            const int ci = tig + ks*8;
            uint32_t bhf[4][2], blf[4][2];
            #pragma unroll
            for (int ni=0;ni<4;ni++){
                int n = (wn*32 + ni*8 + gid)*20;
                bhf[ni][0] = sBh[n + ci];  bhf[ni][1] = sBh[n + ci + 4];
                blf[ni][0] = sBl[n + ci];  blf[ni][1] = sBl[n + ci + 4];
            }
            #pragma unroll
            for (int mi=0;mi<4;mi++){
                int m0 = (wm*64 + mi*16 + gid)*20;
                uint32_t ah[4] = {sAh[m0+ci], sAh[m0+160+ci], sAh[m0+ci+4], sAh[m0+160+ci+4]};
                uint32_t al[4] = {sAl[m0+ci], sAl[m0+160+ci], sAl[m0+ci+4], sAl[m0+160+ci+4]};
                #pragma unroll
                for (int ni=0;ni<4;ni++){
                    mma16816(acc[mi][ni], ah, bhf[ni]);
                    mma16816(acc[mi][ni], ah, blf[ni]);
                    mma16816(acc[mi][ni], al, bhf[ni]);
                }
            }
        }
    }

    #pragma unroll
    for (int mi=0;mi<4;mi++){
        int row = bm + wm*64 + mi*16 + gid;
        #pragma unroll
        for (int ni=0;ni<4;ni++){
            int col = bn + wn*32 + ni*8 + tig*2;
            float2 v0 = make_float2(acc[mi][ni][0], acc[mi][ni][1]);
            float2 v1 = make_float2(acc[mi][ni][2], acc[mi][ni][3]);
            if (bias){
                float2 bb = *(const float2*)(bias + col);
                v0.x += bb.x; v0.y += bb.y; v1.x += bb.x; v1.y += bb.y;
            }
            if (RELU){
                v0.x=fmaxf(v0.x,0.f); v0.y=fmaxf(v0.y,0.f);
                v1.x=fmaxf(v1.x,0.f); v1.y=fmaxf(v1.y,0.f);
            }
            *(float2*)(Cb + (size_t)row    *N + col) = v0;
            *(float2*)(Cb + (size_t)(row+8)*N + col) = v1;
        }
    }
}

// ============================================================================
// Fused attention exp kernel (tensor-core):
// per (b,h,i0): logits = Q*K^T/8 via bf16-split mma, E = exp(logits);
// row-sums -> sinv = 0.125/S ; store E to P for causal tiles (j0 <= i0).
// Dynamic smem: Qh,Ql,Kh,Kl each [128][36] uint32 (stride 36 -> conflict-free)
// ============================================================================
__global__ __launch_bounds__(256) void attn_exp(
    const float* __restrict__ qk, float* __restrict__ P, float* __restrict__ sinv)
{
    extern __shared__ uint32_t sm[];
    uint32_t* sQh = sm;
    uint32_t* sQl = sm + 128*36;
    uint32_t* sKh = sm + 2*128*36;
    uint32_t* sKl = sm + 3*128*36;
    __shared__ float sred[128];

    const int bh = blockIdx.x;
    const int ti = blockIdx.y;          // i-tile index
    const int i0 = ti * 128;
    const int b  = bh >> 3, h = bh & 7;
    const float* qbase = qk + (size_t)(b*Lq)*1024 + h*64;
    const float* kbase = qbase + 512;

    const int t = threadIdx.x;
    const int lane = t & 31, wid = t >> 5;
    const int wm = wid >> 2, wn = wid & 3;
    const int gid = lane >> 2, tig = lane & 3;

    if (t < 128) sred[t] = 0.f;

    // load + split Q tile [128 x 64]
    {
        const int fr = t >> 1, half = t & 1;
        const float* src = qbase + (size_t)(i0 + fr)*1024 + half*32;
        uint32_t* dh = sQh + fr*36 + half*16;
        uint32_t* dl = sQl + fr*36 + half*16;
        #pragma unroll
        for (int j=0;j<8;j++){
            float4 v = *(const float4*)(src + 4*j);
            uint32_t h0,l0,h1,l1;
            bsplit(v.x, v.y, h0, l0);
            bsplit(v.z, v.w, h1, l1);
            dh[2*j] = h0; dh[2*j+1] = h1;
            dl[2*j] = l0; dl[2*j+1] = l1;
        }
    }

    float rsum[4][2];
    #pragma unroll
    for (int mi=0;mi<4;mi++){ rsum[mi][0]=0.f; rsum[mi][1]=0.f; }

    for (int jt = 0; jt < Lq/128; jt++){
        const int j0 = jt * 128;
        __syncthreads();
        // load + split K tile [128 x 64]
        {
            const int fr = t >> 1, half = t & 1;
            const float* src = kbase + (size_t)(j0 + fr)*1024 + half*32;
            uint32_t* dh = sKh + fr*36 + half*16;
            uint32_t* dl = sKl + fr*36 + half*16;
            #pragma unroll
            for (int j=0;j<8;j++){
                float4 v = *(const float4*)(src + 4*j);
                uint32_t h0,l0,h1,l1;
                bsplit(v.x, v.y, h0, l0);
                bsplit(v.z, v.w, h1, l1);
                dh[2*j] = h0; dh[2*j+1] = h1;
                dl[2*j] = l0; dl[2*j+1] = l1;
            }
        }
        __syncthreads();

        float acc[4][4][4];
        #pragma unroll
        for (int i=0;i<4;i++)
            #pragma unroll
            for (int j=0;j<4;j++)
                #pragma unroll
                for (int q=0;q<4;q++) acc[i][j][q] = 0.f;

        #pragma unroll
        for (int ks=0; ks<4; ks++){
            const int ci = tig + ks*8;
            uint32_t bhf[4][2], blf[4][2];
            #pragma unroll
            for (int ni=0;ni<4;ni++){
                int n = (wn*32 + ni*8 + gid)*36;
                bhf[ni][0] = sKh[n + ci];  bhf[ni][1] = sKh[n + ci + 4];
                blf[ni][0] = sKl[n + ci];  blf[ni][1] = sKl[n + ci + 4];
            }
            #pragma unroll
            for (int mi=0;mi<4;mi++){
                int m0 = (wm*64 + mi*16 + gid)*36;
                uint32_t ah[4] = {sQh[m0+ci], sQh[m0+288+ci], sQh[m0+ci+4], sQh[m0+288+ci+4]};
                uint32_t al[4] = {sQl[m0+ci], sQl[m0+288+ci], sQl[m0+ci+4], sQl[m0+288+ci+4]};
                #pragma unroll
                for (int ni=0;ni<4;ni++){
                    mma16816(acc[mi][ni], ah, bhf[ni]);
                    mma16816(acc[mi][ni], ah, blf[ni]);
                    mma16816(acc[mi][ni], al, bhf[ni]);
                }
            }
        }

        // exp, rowsum, optional causal store
        const bool store = (jt <= ti);
        #pragma unroll
        for (int mi=0;mi<4;mi++){
            const int row = i0 + wm*64 + mi*16 + gid;
            #pragma unroll
            for (int ni=0;ni<4;ni++){
                float e0 = __expf(acc[mi][ni][0] * 0.125f);
                float e1 = __expf(acc[mi][ni][1] * 0.125f);
                float e2 = __expf(acc[mi][ni][2] * 0.125f);
                float e3 = __expf(acc[mi][ni][3] * 0.125f);
                rsum[mi][0] += e0 + e1;
                rsum[mi][1] += e2 + e3;
                if (store){
                    const int col = j0 + wn*32 + ni*8 + tig*2;
                    float* p0 = P + ((size_t)bh*Lq + row)*Lq + col;
                    *(float2*)p0            = make_float2(e0, e1);
                    *(float2*)(p0 + 8*Lq)   = make_float2(e2, e3);
                }
            }
        }
    }

    // reduce rsum across tig quad, then across wn warps via shared atomics
    #pragma unroll
    for (int mi=0;mi<4;mi++){
        float r0 = rsum[mi][0], r1 = rsum[mi][1];
        r0 += __shfl_xor_sync(0xffffffffu, r0, 1);
        r0 += __shfl_xor_sync(0xffffffffu, r0, 2);
        r1 += __shfl_xor_sync(0xffffffffu, r1, 1);
        r1 += __shfl_xor_sync(0xffffffffu, r1, 2);
        if (tig == 0){
            atomicAdd(&sred[wm*64 + mi*16 + gid    ], r0);
            atomicAdd(&sred[wm*64 + mi*16 + gid + 8], r1);
        }
    }
    __syncthreads();
    if (t < 128)
        sinv[(size_t)bh*Lq + i0 + t] = 0.125f / sred[t];
}

// ============================================================================
// A[b,i,j] = sum_h P[b,h,i,j] * sinv[b,h,i]   (causal tiles only; memory-bound)
// ============================================================================
__global__ __launch_bounds__(256) void attn_accum(
    const float* __restrict__ P, const float* __restrict__ sinv, float* __restrict__ A)
{
    const int tj = blockIdx.x, ti = blockIdx.y, b = blockIdx.z;
    if (tj > ti) return;
    const int i0 = ti*128, j0 = tj*128;
    __shared__ float ss[8][128];
    const int t = threadIdx.x;
    #pragma unroll
    for (int u=0;u<4;u++){
        int idx = t + u*256;
        int h = idx >> 7, r = idx & 127;
        ss[h][r] = sinv[((size_t)(b*Hq + h))*Lq + i0 + r];
    }
    __syncthreads();
    const size_t bs = (size_t)b*Hq*Lq*Lq;
    #pragma unroll
    for (int u=0;u<16;u++){
        int idx = t + u*256;
        int r = idx >> 5, c = (idx & 31)*4;
        float4 a = make_float4(0.f,0.f,0.f,0.f);
        #pragma unroll
        for (int h=0; h<8; h++){
            const float4 p = *(const float4*)(P + bs + ((size_t)h*Lq + i0 + r)*Lq + j0 + c);
            float s = ss[h][r];
            a.x = fmaf(p.x, s, a.x); a.y = fmaf(p.y, s, a.y);
            a.z = fmaf(p.z, s, a.z); a.w = fmaf(p.w, s, a.w);
        }
        *(float4*)(A + ((size_t)(b*Lq) + i0 + r)*Lq + j0 + c) = a;
    }
}

// ============================================================================
// Batched transpose: xt[b][e][l] = x[b][l][e]
// ============================================================================
__global__ __launch_bounds__(256) void transpose_x(
    const float* __restrict__ x, float* __restrict__ xt)
{
    __shared__ float tile[32][33];
    const int b  = blockIdx.z;
    const int l0 = blockIdx.y * 32, e0 = blockIdx.x * 32;
    const float* xp  = x  + (size_t)b * Lq * Eq;
    float*       xtp = xt + (size_t)b * Eq * Lq;
    const int tx = threadIdx.x, ty = threadIdx.y;
    #pragma unroll
    for (int j=0;j<32;j+=8)
        tile[ty+j][tx] = xp[(size_t)(l0+ty+j)*Eq + e0 + tx];
    __syncthreads();
    #pragma unroll
    for (int j=0;j<32;j+=8)
        xtp[(size_t)(e0+ty+j)*Lq + l0 + tx] = tile[tx][ty+j];
}

// ============================================================================
// W = softmax_j<=i ( A + exp(-(i-j)*0.1) ), strict-causal zeros elsewhere.
// ============================================================================
__global__ __launch_bounds__(256) void make_w(float* __restrict__ A)
{
    const int row = blockIdx.x;
    const int i   = row & (Lq-1);
    float* a = A + (size_t)row * Lq;
    const int t = threadIdx.x;
    float v[4]; float s = 0.f;
    #pragma unroll
    for (int u=0;u<4;u++){
        int j = t + 256*u;
        float val = 0.f;
        if (j <= i){
            float pos = __expf((float)(j - i) * 0.1f);
            val = __expf(a[j] + pos);
        }
        v[u] = val; s += val;
    }
    s = warp_sum(s);
    __shared__ float red[8];
    if ((t & 31) == 0) red[t >> 5] = s;
    __syncthreads();
    float tot = 0.f;
    #pragma unroll
    for (int w=0;w<8;w++) tot += red[w];
    float inv = 1.f / tot;
    #pragma unroll
    for (int u=0;u<4;u++){
        int j = t + 256*u;
        a[j] = v[u] * inv;
    }
}

// ============================================================================
// LayerNorm kernels: one warp per 512-wide row
// ============================================================================
__global__ __launch_bounds__(256) void add_ln2(
    const float* __restrict__ x, const float* __restrict__ y,
    const float* __restrict__ g1, const float* __restrict__ b1,
    const float* __restrict__ g2, const float* __restrict__ b2,
    float* __restrict__ out)
{
    const int row  = blockIdx.x * 8 + (threadIdx.x >> 5);
    const int lane = threadIdx.x & 31;
    const float* xr = x + (size_t)row * Eq;
    const float* yr = y + (size_t)row * Eq;
    float v[16]; float s = 0.f;
    #pragma unroll
    for (int u=0;u<16;u++){ int c = lane + u*32; v[u] = xr[c] + yr[c]; s += v[u]; }
    s = warp_sum(s);
    float mean = s * (1.0f/Eq);
    float sq = 0.f;
    #pragma unroll
    for (int u=0;u<16;u++){ float d = v[u]-mean; sq += d*d; }
    sq = warp_sum(sq);
    float rstd = rsqrtf(sq*(1.0f/Eq) + 1e-5f);
    float s2 = 0.f;
    #pragma unroll
    for (int u=0;u<16;u++){ int c = lane + u*32; v[u] = (v[u]-mean)*rstd*g1[c] + b1[c]; s2 += v[u]; }
    s2 = warp_sum(s2);
    float m2 = s2 * (1.0f/Eq);
    float q2 = 0.f;
    #pragma unroll
    for (int u=0;u<16;u++){ float d = v[u]-m2; q2 += d*d; }
    q2 = warp_sum(q2);
    float r2 = rsqrtf(q2*(1.0f/Eq) + 1e-5f);
    float* orow = out + (size_t)row * Eq;
    #pragma unroll
    for (int u=0;u<16;u++){ int c = lane + u*32; orow[c] = (v[u]-m2)*r2*g2[c] + b2[c]; }
}

__global__ __launch_bounds__(256) void add_ln1(
    const float* __restrict__ x, const float* __restrict__ y,
    const float* __restrict__ g, const float* __restrict__ b,
    float* __restrict__ out)
{
    const int row  = blockIdx.x * 8 + (threadIdx.x >> 5);
    const int lane = threadIdx.x & 31;
    const float* xr = x + (size_t)row * Eq;
    const float* yr = y + (size_t)row * Eq;
    float v[16]; float s = 0.f;
    #pragma unroll
    for (int u=0;u<16;u++){ int c = lane + u*32; v[u] = xr[c] + yr[c]; s += v[u]; }
    s = warp_sum(s);
    float mean = s * (1.0f/Eq);
    float sq = 0.f;
    #pragma unroll
    for (int u=0;u<16;u++){ float d = v[u]-mean; sq += d*d; }
    sq = warp_sum(sq);
    float rstd = rsqrtf(sq*(1.0f/Eq) + 1e-5f);
    float* orow = out + (size_t)row * Eq;
    #pragma unroll
    for (int u=0;u<16;u++){ int c = lane + u*32; orow[c] = (v[u]-mean)*rstd*g[c] + b[c]; }
}

// ============================================================================
// Launch
// ============================================================================
extern "C" void kernel_launch(void* const* d_in, const int* in_sizes, int n_in,
                              void* d_out, int out_size)
{
    const float* input = (const float*)d_in[0];
    const float* Wqkv  = (const float*)d_in[1];
    const float* bqkv  = (const float*)d_in[2];
    const float* W1    = (const float*)d_in[3];
    const float* b1    = (const float*)d_in[4];
    const float* W2    = (const float*)d_in[5];
    const float* b2    = (const float*)d_in[6];
    const float* g1    = (const float*)d_in[7];
    const float* bt1   = (const float*)d_in[8];
    const float* g2    = (const float*)d_in[9];
    const float* bt2   = (const float*)d_in[10];
    const float* g3    = (const float*)d_in[11];
    const float* bt3   = (const float*)d_in[12];

    float *x, *qk, *sv, *A, *tb, *hb, *xt, *P;
    cudaGetSymbolAddress((void**)&x,  g_x);
    cudaGetSymbolAddress((void**)&qk, g_qk);
    cudaGetSymbolAddress((void**)&sv, g_sv);
    cudaGetSymbolAddress((void**)&A,  g_A);
    cudaGetSymbolAddress((void**)&tb, g_t);
    cudaGetSymbolAddress((void**)&hb, g_h);
    cudaGetSymbolAddress((void**)&xt, g_xt);
    cudaGetSymbolAddress((void**)&P,  g_P);

    const int ATTN_SMEM = 4 * 128 * 36 * 4;   // 73728 B dynamic
    cudaFuncSetAttribute(attn_exp, cudaFuncAttributeMaxDynamicSharedMemorySize, ATTN_SMEM);

    cudaMemcpyAsync(x, input, (size_t)Mq*Eq*sizeof(float),
                    cudaMemcpyDeviceToDevice, 0);

    for (int d = 0; d < 4; d++){
        const float* Wq = Wqkv + (size_t)d * 1536 * 512;
        const float* bq = bqkv + (size_t)d * 1536;

        // q|k projection (v/out-proj of Wqkv are dead in the reference)
        mma_gemm<0><<<dim3(1024/128, Mq/128, 1), 256>>>(
            x, Wq, bq, qk, Mq, 1024, 512, 0, 0, 0, 0);

        // fused tensor-core logits+exp (stores causal P, computes sinv)
        attn_exp<<<dim3(Bq*Hq, Lq/128), 256, ATTN_SMEM>>>(qk, P, sv);

        // head-averaged A over causal tiles (memory-bound)
        attn_accum<<<dim3(Lq/128, Lq/128, Bq), 256>>>(P, sv, A);

        // second softmax with causal mask + relative-position bias (in place)
        make_w<<<Bq*Lq, 256>>>(A);

        // sa = W @ x: transpose x per batch, then NT tensor-core GEMM w/ causal cutoff
        transpose_x<<<dim3(Eq/32, Lq/32, Bq), dim3(32,8)>>>(x, xt);
        mma_gemm<0><<<dim3(Eq/128, Lq/128, Bq), 256>>>(
            A, xt, nullptr, tb, Lq, Eq, Lq,
            (long)Lq*Lq, (long)Eq*Lq, (long)Lq*Eq, 1);

        // x = LN2(LN1(x + sa))   (cross-attn block is a double-LN no-op)
        add_ln2<<<Mq/8, 256>>>(x, tb,
                               g1 + d*Eq, bt1 + d*Eq,
                               g2 + d*Eq, bt2 + d*Eq, x);

        // FFN
        mma_gemm<1><<<dim3(FFq/128, Mq/128, 1), 256>>>(
            x, W1 + (size_t)d*FFq*Eq, b1 + (size_t)d*FFq, hb,
            Mq, FFq, Eq, 0, 0, 0, 0);
        mma_gemm<0><<<dim3(Eq/128, Mq/128, 1), 256>>>(
            hb, W2 + (size_t)d*Eq*FFq, b2 + (size_t)d*Eq, tb,
            Mq, Eq, FFq, 0, 0, 0, 0);

        float* outp = (d == 3) ? (float*)d_out : x;
        add_ln1<<<Mq/8, 256>>>(x, tb, g3 + d*Eq, bt3 + d*Eq, outp);
    }
}